// round 5
// baseline (speedup 1.0000x reference)
#include <cuda_runtime.h>

// Depthwise Conv1d: B=32, C=128, L=8192, kernel=3, stride=1, pad=1, fp32.
// out[b,c,l] = w[c,0]*x[b,c,l-1] + w[c,1]*x[b,c,l] + w[c,2]*x[b,c,l+1] + bias[c]
//
// R5: R4 (grid-strided ILP=4, fully coalesced per-instruction) + hoisted
// per-channel taps. The grid stride is exactly 1024 rows, and 1024 % 128 == 0,
// so all ITER iterations of a thread land on the SAME channel -> load
// w0/w1/w2/bias once instead of per-iteration (removes 12 scalar LDGs and
// a pile of index ALU per thread).

#define BATCH 32
#define CHANS 128
#define LEN   8192
#define LEN4  (LEN / 4)          // 2048 float4 per row
#define ROWS  (BATCH * CHANS)    // 4096
#define NTHREADS 256
#define ITER 4
#define TOTAL4   (ROWS * LEN4)               // 8,388,608 float4
#define NTHREADS_TOTAL (TOTAL4 / ITER)       // 2,097,152
#define NBLOCKS  (NTHREADS_TOTAL / NTHREADS) // 8192

// stride in rows between iterations: NTHREADS_TOTAL / LEN4 = 1024 (multiple of CHANS)

__global__ __launch_bounds__(NTHREADS)
void dwconv1d_kernel(const float* __restrict__ x,
                     const float* __restrict__ w,
                     const float* __restrict__ bias,
                     float* __restrict__ out)
{
    const unsigned int gid    = blockIdx.x * NTHREADS + threadIdx.x;
    const unsigned int stride = NTHREADS_TOTAL; // uniform grid stride (float4 units)

    unsigned int idx[ITER], row[ITER], j[ITER];
#pragma unroll
    for (int i = 0; i < ITER; i++) {
        idx[i] = gid + i * stride;
        row[i] = idx[i] >> 11;         // / LEN4
        j[i]   = idx[i] & (LEN4 - 1);  // within-row float4 index
    }

    // Channel is identical across all iterations (stride is a multiple of
    // CHANS rows). Load taps ONCE.
    const unsigned int c = row[0] & (CHANS - 1);
    const float w0 = __ldg(&w[c * 3 + 0]);
    const float w1 = __ldg(&w[c * 3 + 1]);
    const float w2 = __ldg(&w[c * 3 + 2]);
    const float bb = __ldg(&bias[c]);

    // ---- front-batched vector loads (high MLP, fully coalesced) ----
    float4 v[ITER];
#pragma unroll
    for (int i = 0; i < ITER; i++)
        v[i] = reinterpret_cast<const float4*>(x)[idx[i]];

    // ---- halo loads (L1 hits: same/adjacent lines as neighbors' vec loads) ----
    float left[ITER], right[ITER];
#pragma unroll
    for (int i = 0; i < ITER; i++) {
        const float* xs = x + (size_t)row[i] * LEN;
        unsigned int e0 = 4u * j[i];
        left[i]  = (j[i] == 0)        ? 0.0f : __ldg(&xs[e0 - 1]);
        right[i] = (j[i] == LEN4 - 1) ? 0.0f : __ldg(&xs[e0 + 4]);
    }

    // ---- compute + store ----
#pragma unroll
    for (int i = 0; i < ITER; i++) {
        float4 o;
        o.x = fmaf(w0, left[i], fmaf(w1, v[i].x, fmaf(w2, v[i].y, bb)));
        o.y = fmaf(w0, v[i].x,  fmaf(w1, v[i].y, fmaf(w2, v[i].z, bb)));
        o.z = fmaf(w0, v[i].y,  fmaf(w1, v[i].z, fmaf(w2, v[i].w, bb)));
        o.w = fmaf(w0, v[i].z,  fmaf(w1, v[i].w, fmaf(w2, right[i], bb)));
        reinterpret_cast<float4*>(out)[idx[i]] = o;
    }
}

extern "C" void kernel_launch(void* const* d_in, const int* in_sizes, int n_in,
                              void* d_out, int out_size)
{
    const float* x    = (const float*)d_in[0];
    const float* w    = (const float*)d_in[1];
    const float* bias = (const float*)d_in[2];
    float* out        = (float*)d_out;

    dwconv1d_kernel<<<NBLOCKS, NTHREADS>>>(x, w, bias, out);
}